// round 10
// baseline (speedup 1.0000x reference)
#include <cuda_runtime.h>

// out = cumprod_j( cos(w_j) * cos(x @ W_pre^T + b_pre) ) @ W_post^T + b_post
//
// Analytic reduction of the quantum layer:
//   z_j   = cos(q_weights_j) * cos(angle_j)
//   <Z_i> = prod_{j<=i} z_j            (CNOT chain = prefix-XOR)
//
// Block = (row pair, column half): grid=256 x 512 thr, TARGET 3 blocks/SM
// (launch_bounds(512,3) caps regs at ~42) so three blocks' stall phases
// mutually overlap. W_pre loaded in-loop (short register lifetimes);
// W_post column register-cached, reused by both rows; per-warp redundant
// prefix scan (only two block-wide barriers).

#define NQ   16
#define DIN  1024
#define DOUT 1024
#define B    256

__global__ __launch_bounds__(512, 3)
void quantum_projector_kernel(const float* __restrict__ x,
                              const float* __restrict__ W_pre,
                              const float* __restrict__ b_pre,
                              const float* __restrict__ q_weights,
                              const float* __restrict__ W_post,
                              const float* __restrict__ b_post,
                              float* __restrict__ out)
{
    __shared__ float4 sx0[DIN / 4];      // 4 KB: row r0
    __shared__ float4 sx1[DIN / 4];      // 4 KB: row r1
    __shared__ float  s_angle[2 * NQ];   // [row][qubit]
    __shared__ float4 s_wz[16][8];       // warp-private scan slots

    const int bx   = blockIdx.x;
    const int pair = bx >> 1;            // which row pair
    const int half = bx & 1;             // which 512-column half
    const int r0   = pair * 2;
    const int r1   = r0 + 1;
    const int tid  = threadIdx.x;
    const int warp = tid >> 5;           // 16 warps = 16 qubits
    const int lane = tid & 31;

    // ---- Stage both x rows into smem (512 threads, one float4 each) ----
    {
        const float4* __restrict__ x4 = reinterpret_cast<const float4*>(x);
        if (tid < 256) sx0[tid]       = x4[r0 * (DIN / 4) + tid];
        else           sx1[tid - 256] = x4[r1 * (DIN / 4) + (tid - 256)];
    }

    // ---- Prefetch this thread's W_post column (shared by both rows) ----
    const int col = half * 512 + tid;
    const float4* __restrict__ Wp4 = reinterpret_cast<const float4*>(W_post);
    float4 wreg[4];
#pragma unroll
    for (int i = 0; i < 4; i++)
        wreg[i] = Wp4[col * 4 + i];
    const float bp = b_post[col];

    __syncthreads();   // barrier 1: x staged

    // ---- Phase 1: both rows' angle[warp]; W_pre in-loop (short lifetimes) ----
    {
        const float4* __restrict__ w4 = reinterpret_cast<const float4*>(W_pre + warp * DIN);
        float a0e = 0.f, a0o = 0.f, a1e = 0.f, a1o = 0.f;
#pragma unroll
        for (int i = 0; i < 4; i++) {
            const int ke = lane + 64 * i;
            const int ko = ke + 32;
            const float4 we = w4[ke], wo = w4[ko];
            const float4 xe0 = sx0[ke], xo0 = sx0[ko];
            const float4 xe1 = sx1[ke], xo1 = sx1[ko];
            a0e += xe0.x * we.x + xe0.y * we.y + xe0.z * we.z + xe0.w * we.w;
            a0o += xo0.x * wo.x + xo0.y * wo.y + xo0.z * wo.z + xo0.w * wo.w;
            a1e += xe1.x * we.x + xe1.y * we.y + xe1.z * we.z + xe1.w * we.w;
            a1o += xo1.x * wo.x + xo1.y * wo.y + xo1.z * wo.z + xo1.w * wo.w;
        }
        float acc0 = a0e + a0o;
        float acc1 = a1e + a1o;
#pragma unroll
        for (int off = 16; off >= 1; off >>= 1) {
            acc0 += __shfl_xor_sync(0xffffffffu, acc0, off);
            acc1 += __shfl_xor_sync(0xffffffffu, acc1, off);
        }
        if (lane == 0) {
            const float b = b_pre[warp];
            s_angle[warp]      = acc0 + b;
            s_angle[NQ + warp] = acc1 + b;
        }
    }
    __syncthreads();   // barrier 2: angles ready

    // ---- Phase 2: EVERY warp computes the dual-row prefix scan ----
    // lanes 0..15 -> row0, lanes 16..31 -> row1 (segmented shfl_up scan),
    // broadcast within the warp via its private smem slot (no block barrier).
    {
        const int q   = lane & 15;
        const int seg = lane >> 4;
        float v = __cosf(q_weights[q]) * __cosf(s_angle[seg * NQ + q]);
#pragma unroll
        for (int off = 1; off <= 8; off <<= 1) {
            float t = __shfl_up_sync(0xffffffffu, v, off);
            if (q >= off) v *= t;   // segment boundary: q < off blocks carry-in
        }
        reinterpret_cast<float*>(s_wz[warp])[lane] = v;
        __syncwarp();
    }

    // ---- Phase 3: one column x 2 rows per thread; zq via LDS.128 ----
    float d0 = bp, d1 = bp;
#pragma unroll
    for (int i = 0; i < 4; i++) {
        const float4 za = s_wz[warp][i];       // row0 qubits 4i..4i+3
        const float4 zb = s_wz[warp][4 + i];   // row1
        const float4 w  = wreg[i];
        d0 += za.x * w.x + za.y * w.y + za.z * w.z + za.w * w.w;
        d1 += zb.x * w.x + zb.y * w.y + zb.z * w.z + zb.w * w.w;
    }

    out[r0 * DOUT + col] = d0;
    out[r1 * DOUT + col] = d1;
}

extern "C" void kernel_launch(void* const* d_in, const int* in_sizes, int n_in,
                              void* d_out, int out_size)
{
    const float* x         = (const float*)d_in[0];   // [256, 1024]
    const float* W_pre     = (const float*)d_in[1];   // [16, 1024]
    const float* b_pre     = (const float*)d_in[2];   // [16]
    const float* q_weights = (const float*)d_in[3];   // [16]
    const float* W_post    = (const float*)d_in[4];   // [1024, 16]
    const float* b_post    = (const float*)d_in[5];   // [1024]
    float* out             = (float*)d_out;           // [256, 1024]

    quantum_projector_kernel<<<B, 512>>>(x, W_pre, b_pre, q_weights,
                                         W_post, b_post, out);
}

// round 11
// speedup vs baseline: 1.0143x; 1.0143x over previous
#include <cuda_runtime.h>

// out = cumprod_j( cos(w_j) * cos(x @ W_pre^T + b_pre) ) @ W_post^T + b_post
//
// Analytic reduction of the quantum layer:
//   z_j   = cos(q_weights_j) * cos(angle_j)
//   <Z_i> = prod_{j<=i} z_j            (CNOT chain = prefix-XOR)
//
// Block = (row pair, column half): grid=256 x 512 thr, 2 blocks/SM
// (launch_bounds(512,2): 64-reg budget — R8-validated, no spills).
//   - W_post column register-cached, reused by both rows (validated win)
//   - W_pre loaded in-loop (short lifetimes; wv-prefetch proven useless at 64 regs)
//   - ONLY TWO block barriers; prefix scan computed redundantly per warp and
//     broadcast via warp-private smem + __syncwarp (validated correct in R10)
//   - phase-3 zq reads are uniform-address LDS.128 (broadcast, 1 phase each)

#define NQ   16
#define DIN  1024
#define DOUT 1024
#define B    256

__global__ __launch_bounds__(512, 2)
void quantum_projector_kernel(const float* __restrict__ x,
                              const float* __restrict__ W_pre,
                              const float* __restrict__ b_pre,
                              const float* __restrict__ q_weights,
                              const float* __restrict__ W_post,
                              const float* __restrict__ b_post,
                              float* __restrict__ out)
{
    __shared__ float4 sx0[DIN / 4];      // 4 KB: row r0
    __shared__ float4 sx1[DIN / 4];      // 4 KB: row r1
    __shared__ float  s_angle[2 * NQ];   // [row][qubit]
    __shared__ float4 s_wz[16][8];       // warp-private scan slots

    const int bx   = blockIdx.x;
    const int pair = bx >> 1;            // which row pair
    const int half = bx & 1;             // which 512-column half
    const int r0   = pair * 2;
    const int r1   = r0 + 1;
    const int tid  = threadIdx.x;
    const int warp = tid >> 5;           // 16 warps = 16 qubits
    const int lane = tid & 31;

    // ---- Stage both x rows into smem (512 threads, one float4 each) ----
    {
        const float4* __restrict__ x4 = reinterpret_cast<const float4*>(x);
        if (tid < 256) sx0[tid]       = x4[r0 * (DIN / 4) + tid];
        else           sx1[tid - 256] = x4[r1 * (DIN / 4) + (tid - 256)];
    }

    // ---- Prefetch this thread's W_post column (shared by both rows) ----
    const int col = half * 512 + tid;
    const float4* __restrict__ Wp4 = reinterpret_cast<const float4*>(W_post);
    float4 wreg[4];
#pragma unroll
    for (int i = 0; i < 4; i++)
        wreg[i] = Wp4[col * 4 + i];
    const float bp = b_post[col];

    __syncthreads();   // barrier 1: x staged

    // ---- Phase 1: both rows' angle[warp]; W_pre in-loop (short lifetimes) ----
    {
        const float4* __restrict__ w4 = reinterpret_cast<const float4*>(W_pre + warp * DIN);
        float a0e = 0.f, a0o = 0.f, a1e = 0.f, a1o = 0.f;
#pragma unroll
        for (int i = 0; i < 4; i++) {
            const int ke = lane + 64 * i;
            const int ko = ke + 32;
            const float4 we = w4[ke], wo = w4[ko];
            const float4 xe0 = sx0[ke], xo0 = sx0[ko];
            const float4 xe1 = sx1[ke], xo1 = sx1[ko];
            a0e += xe0.x * we.x + xe0.y * we.y + xe0.z * we.z + xe0.w * we.w;
            a0o += xo0.x * wo.x + xo0.y * wo.y + xo0.z * wo.z + xo0.w * wo.w;
            a1e += xe1.x * we.x + xe1.y * we.y + xe1.z * we.z + xe1.w * we.w;
            a1o += xo1.x * wo.x + xo1.y * wo.y + xo1.z * wo.z + xo1.w * wo.w;
        }
        float acc0 = a0e + a0o;
        float acc1 = a1e + a1o;
#pragma unroll
        for (int off = 16; off >= 1; off >>= 1) {
            acc0 += __shfl_xor_sync(0xffffffffu, acc0, off);
            acc1 += __shfl_xor_sync(0xffffffffu, acc1, off);
        }
        if (lane == 0) {
            const float b = b_pre[warp];
            s_angle[warp]      = acc0 + b;
            s_angle[NQ + warp] = acc1 + b;
        }
    }
    __syncthreads();   // barrier 2: angles ready

    // ---- Phase 2: EVERY warp computes the dual-row prefix scan ----
    // lanes 0..15 -> row0, lanes 16..31 -> row1 (segmented shfl_up scan),
    // broadcast within the warp via its private smem slot (no block barrier).
    {
        const int q   = lane & 15;
        const int seg = lane >> 4;
        float v = __cosf(q_weights[q]) * __cosf(s_angle[seg * NQ + q]);
#pragma unroll
        for (int off = 1; off <= 8; off <<= 1) {
            float t = __shfl_up_sync(0xffffffffu, v, off);
            if (q >= off) v *= t;   // segment boundary: q < off blocks carry-in
        }
        reinterpret_cast<float*>(s_wz[warp])[lane] = v;
        __syncwarp();
    }

    // ---- Phase 3: one column x 2 rows per thread; zq via broadcast LDS.128 ----
    float d0 = bp, d1 = bp;
#pragma unroll
    for (int i = 0; i < 4; i++) {
        const float4 za = s_wz[warp][i];       // row0 qubits 4i..4i+3
        const float4 zb = s_wz[warp][4 + i];   // row1
        const float4 w  = wreg[i];
        d0 += za.x * w.x + za.y * w.y + za.z * w.z + za.w * w.w;
        d1 += zb.x * w.x + zb.y * w.y + zb.z * w.z + zb.w * w.w;
    }

    out[r0 * DOUT + col] = d0;
    out[r1 * DOUT + col] = d1;
}

extern "C" void kernel_launch(void* const* d_in, const int* in_sizes, int n_in,
                              void* d_out, int out_size)
{
    const float* x         = (const float*)d_in[0];   // [256, 1024]
    const float* W_pre     = (const float*)d_in[1];   // [16, 1024]
    const float* b_pre     = (const float*)d_in[2];   // [16]
    const float* q_weights = (const float*)d_in[3];   // [16]
    const float* W_post    = (const float*)d_in[4];   // [1024, 16]
    const float* b_post    = (const float*)d_in[5];   // [1024]
    float* out             = (float*)d_out;           // [256, 1024]

    quantum_projector_kernel<<<B, 512>>>(x, W_pre, b_pre, q_weights,
                                         W_post, b_post, out);
}